// round 1
// baseline (speedup 1.0000x reference)
#include <cuda_runtime.h>
#include <math.h>

// Problem constants (fixed shapes per reference)
#define BB    32
#define HH    112
#define WW    112
#define AA    9
#define NBOX  768          // B * 24
#define NCELL 3612672      // B*H*W*A
#define NFLT  18063360     // NCELL * 5
#define NF4   (NFLT/4)     // 4515840

#define A_BLOCKS 1184
#define A_THREADS 256

__device__ float g_partials[A_BLOCKS];

__device__ __forceinline__ float softplus_f(float x) {
    // log1p(exp(x)) stable == max(x,0) + log1p(exp(-|x|))
    return fmaxf(x, 0.0f) + log1pf(expf(-fabsf(x)));
}

// Kernel A: sum softplus over the obj channel (every 5th float, offset 4),
// reading the whole tensor with coalesced float4 loads.
// Each float4 at index i covers floats [4i, 4i+3]; it contains the obj
// element iff i%5 != 0, at lane (i%5 - 1).
__global__ __launch_bounds__(A_THREADS) void objsum_kernel(const float* __restrict__ pred) {
    const float4* __restrict__ p4 = reinterpret_cast<const float4*>(pred);
    float acc = 0.0f;
    int stride = gridDim.x * blockDim.x;
    for (int i = blockIdx.x * blockDim.x + threadIdx.x; i < NF4; i += stride) {
        float4 v = p4[i];
        int m = i % 5;
        if (m != 0) {
            float x = (m == 1) ? v.x : (m == 2) ? v.y : (m == 3) ? v.z : v.w;
            acc += softplus_f(x);
        }
    }
    __shared__ float s[A_THREADS];
    s[threadIdx.x] = acc;
    __syncthreads();
    for (int o = A_THREADS / 2; o > 0; o >>= 1) {
        if (threadIdx.x < o) s[threadIdx.x] += s[threadIdx.x + o];
        __syncthreads();
    }
    if (threadIdx.x == 0) g_partials[blockIdx.x] = s[0];
}

// Kernel B: single block. Builds the 768 scatter keys + target values,
// dedups (last index wins within a batch, matching sequential scatter .set),
// gathers predictions at responsible cells, reduces partials, finalizes.
__global__ __launch_bounds__(256) void finalize_kernel(const float* __restrict__ pred,
                                                       const float* __restrict__ bbox,
                                                       float* __restrict__ out) {
    __shared__ int   s_key[NBOX];
    __shared__ float s_t[NBOX][4];

    // anchors computed in double, stored fp32 (matches jnp.asarray(..., float32))
    float aw[AA], ah[AA];
    {
        const double S[3] = {32.0, 64.0, 128.0};
        const double R[3] = {0.5, 1.0, 2.0};
        #pragma unroll
        for (int i = 0; i < AA; i++) {
            double s = S[i / 3], r = R[i % 3];
            aw[i] = (float)(s * sqrt(r) / 224.0);
            ah[i] = (float)(s / sqrt(r) / 224.0);
        }
    }

    int tid = threadIdx.x;

    for (int idx = tid; idx < NBOX; idx += 256) {
        float cx = bbox[idx * 4 + 0];
        float cy = bbox[idx * 4 + 1];
        float w  = bbox[idx * 4 + 2];
        float h  = bbox[idx * 4 + 3];
        bool valid = (cx != 0.0f) || (cy != 0.0f) || (w != 0.0f) || (h != 0.0f);
        if (!valid) { s_key[idx] = -1; continue; }

        int gx = (int)floorf(cx * (float)WW); gx = min(max(gx, 0), WW - 1);
        int gy = (int)floorf(cy * (float)HH); gy = min(max(gy, 0), HH - 1);

        float wh = w * h;
        int best = 0; float bi = -1e30f;
        #pragma unroll
        for (int a = 0; a < AA; a++) {
            float inter = fminf(w, aw[a]) * fminf(h, ah[a]);
            float uni   = wh + aw[a] * ah[a] - inter;
            float iou   = inter / (uni + 1e-16f);
            if (iou > bi) { bi = iou; best = a; }   // first max wins (strict >)
        }

        int b = idx / 24;
        s_key[idx]  = ((b * HH + gy) * WW + gx) * AA + best;
        s_t[idx][0] = cx * (float)WW - (float)gx;
        s_t[idx][1] = cy * (float)HH - (float)gy;
        s_t[idx][2] = logf(w / aw[best] + 1e-16f);
        s_t[idx][3] = logf(h / ah[best] + 1e-16f);
    }
    __syncthreads();

    float coord = 0.0f, objs = 0.0f, sppos = 0.0f;
    int npos = 0;

    for (int idx = tid; idx < NBOX; idx += 256) {
        int key = s_key[idx];
        if (key < 0) continue;
        // collisions only possible within the same batch (key includes b);
        // last scatter index wins -> idx is winner iff no later same-batch box has same key
        int bend = ((idx / 24) + 1) * 24;
        bool win = true;
        for (int j = idx + 1; j < bend; j++) {
            if (s_key[j] == key) { win = false; break; }
        }
        if (!win) continue;

        const float* p = pred + (long long)key * 5;
        float d0 = p[0] - s_t[idx][0];
        float d1 = p[1] - s_t[idx][1];
        float d2 = p[2] - s_t[idx][2];
        float d3 = p[3] - s_t[idx][3];
        coord += d0 * d0 + d1 * d1 + d2 * d2 + d3 * d3;
        float o = p[4];
        objs  += softplus_f(-o);
        sppos += softplus_f(o);
        npos++;
    }

    // sum kernel-A partials
    float sall = 0.0f;
    for (int i = tid; i < A_BLOCKS; i += 256) sall += g_partials[i];

    __shared__ float r0[256], r1[256], r2[256], r3[256];
    __shared__ int rn[256];
    r0[tid] = coord; r1[tid] = objs; r2[tid] = sppos; r3[tid] = sall; rn[tid] = npos;
    __syncthreads();
    for (int o = 128; o > 0; o >>= 1) {
        if (tid < o) {
            r0[tid] += r0[tid + o];
            r1[tid] += r1[tid + o];
            r2[tid] += r2[tid + o];
            r3[tid] += r3[tid + o];
            rn[tid] += rn[tid + o];
        }
        __syncthreads();
    }

    if (tid == 0) {
        float np = (float)rn[0];
        float nn = (float)NCELL - np;
        float c  = 5.0f * r0[0] / fmaxf(np, 1.0f);
        float ob = 1.0f * r1[0] / fmaxf(np, 1.0f);
        float no = 0.5f * (r3[0] - r2[0]) / fmaxf(nn, 1.0f);
        out[0] = c + ob + no;
        out[1] = c;
        out[2] = ob;
        out[3] = no;
        out[4] = 0.0f;
    }
}

extern "C" void kernel_launch(void* const* d_in, const int* in_sizes, int n_in,
                              void* d_out, int out_size) {
    const float* pred = (const float*)d_in[0];
    const float* bbox = (const float*)d_in[1];
    float* out = (float*)d_out;
    (void)in_sizes; (void)n_in; (void)out_size;

    objsum_kernel<<<A_BLOCKS, A_THREADS>>>(pred);
    finalize_kernel<<<1, 256>>>(pred, bbox, out);
}

// round 3
// speedup vs baseline: 1.1829x; 1.1829x over previous
#include <cuda_runtime.h>
#include <math.h>

// Fixed shapes per reference
#define HH    112
#define WW    112
#define AA    9
#define NBOX  768          // B * 24
#define NCELL 3612672      // B*H*W*A
#define NF4   4515840      // total float4s in predictions
#define NTASK 903168       // NF4/5: each task = 5 float4s = 4 records

#define BLOCKS  1184
#define THREADS 256

__device__ float g_partials[BLOCKS];
__device__ int   g_counter = 0;   // zero-inited at module load; last block resets it

// Round-1-proven accurate softplus
__device__ __forceinline__ float softplus_acc(float x) {
    return fmaxf(x, 0.0f) + log1pf(expf(-fabsf(x)));
}

__global__ __launch_bounds__(THREADS) void loss_kernel(const float* __restrict__ pred,
                                                       const float* __restrict__ bbox,
                                                       float* __restrict__ out) {
    // ---------- Phase 1: every block sums softplus over the obj channel ----------
    // Task t covers floats [20t, 20t+19] = 4 records. Obj elements (global idx
    // ≡ 4 mod 5) sit in float4s 5t+1..5t+4 at lanes .x/.y/.z/.w. The float4 at
    // 5t holds only bbox channels and is skipped; every 32B sector is still
    // requested by some lane, so DRAM traffic = one full 72MB pass.
    const float4* __restrict__ p4 = reinterpret_cast<const float4*>(pred);
    float acc = 0.0f;
    const int stride = gridDim.x * blockDim.x;
    for (int t = blockIdx.x * blockDim.x + threadIdx.x; t < NTASK; t += stride) {
        int b = t * 5;
        float4 c1 = p4[b + 1];
        float4 c2 = p4[b + 2];
        float4 c3 = p4[b + 3];
        float4 c4 = p4[b + 4];
        acc += softplus_acc(c1.x);
        acc += softplus_acc(c2.y);
        acc += softplus_acc(c3.z);
        acc += softplus_acc(c4.w);
    }

    __shared__ float s[THREADS];
    const int tid = threadIdx.x;
    s[tid] = acc;
    __syncthreads();
    #pragma unroll
    for (int o = THREADS / 2; o > 0; o >>= 1) {
        if (tid < o) s[tid] += s[tid + o];
        __syncthreads();
    }

    __shared__ bool is_last;
    if (tid == 0) {
        g_partials[blockIdx.x] = s[0];
        __threadfence();
        int old = atomicAdd(&g_counter, 1);
        is_last = (old == (int)gridDim.x - 1);
    }
    __syncthreads();
    if (!is_last) return;

    // ---------- Phase 2: last block only — targets, dedup, gather, finalize ----------
    __shared__ int   s_key[NBOX];
    __shared__ float s_t[NBOX][4];

    // anchors computed in double on device (bit-identical to round-1 pass)
    float aw[AA], ah[AA];
    {
        const double S[3] = {32.0, 64.0, 128.0};
        const double R[3] = {0.5, 1.0, 2.0};
        #pragma unroll
        for (int i = 0; i < AA; i++) {
            double sd = S[i / 3], rd = R[i % 3];
            aw[i] = (float)(sd * sqrt(rd) / 224.0);
            ah[i] = (float)(sd / sqrt(rd) / 224.0);
        }
    }

    for (int idx = tid; idx < NBOX; idx += THREADS) {
        float cx = bbox[idx * 4 + 0];
        float cy = bbox[idx * 4 + 1];
        float w  = bbox[idx * 4 + 2];
        float h  = bbox[idx * 4 + 3];
        bool valid = (cx != 0.0f) || (cy != 0.0f) || (w != 0.0f) || (h != 0.0f);
        if (!valid) { s_key[idx] = -1; continue; }

        int gx = (int)floorf(cx * (float)WW); gx = min(max(gx, 0), WW - 1);
        int gy = (int)floorf(cy * (float)HH); gy = min(max(gy, 0), HH - 1);

        float wh = w * h;
        int best = 0; float bi = -1e30f;
        #pragma unroll
        for (int a = 0; a < AA; a++) {
            float inter = fminf(w, aw[a]) * fminf(h, ah[a]);
            float uni   = wh + aw[a] * ah[a] - inter;
            float iou   = inter / (uni + 1e-16f);
            if (iou > bi) { bi = iou; best = a; }   // first max wins (strict >)
        }

        int b = idx / 24;
        s_key[idx]  = ((b * HH + gy) * WW + gx) * AA + best;
        s_t[idx][0] = cx * (float)WW - (float)gx;
        s_t[idx][1] = cy * (float)HH - (float)gy;
        s_t[idx][2] = logf(w / aw[best] + 1e-16f);
        s_t[idx][3] = logf(h / ah[best] + 1e-16f);
    }
    __syncthreads();

    float coord = 0.0f, objs = 0.0f, sppos = 0.0f;
    int npos = 0;

    for (int idx = tid; idx < NBOX; idx += THREADS) {
        int key = s_key[idx];
        if (key < 0) continue;
        // collisions only possible within the same batch; last scatter wins
        int bend = ((idx / 24) + 1) * 24;
        bool win = true;
        for (int j = idx + 1; j < bend; j++) {
            if (s_key[j] == key) { win = false; break; }
        }
        if (!win) continue;

        const float* p = pred + (long long)key * 5;
        float d0 = p[0] - s_t[idx][0];
        float d1 = p[1] - s_t[idx][1];
        float d2 = p[2] - s_t[idx][2];
        float d3 = p[3] - s_t[idx][3];
        coord += d0 * d0 + d1 * d1 + d2 * d2 + d3 * d3;
        float o = p[4];
        objs  += softplus_acc(-o);
        sppos += softplus_acc(o);
        npos++;
    }

    // reduce partials written by all blocks (fence+atomic chain makes them visible)
    float sall = 0.0f;
    for (int i = tid; i < BLOCKS; i += THREADS) sall += g_partials[i];

    __shared__ float r0[THREADS], r1[THREADS], r2[THREADS], r3[THREADS];
    __shared__ int   rn[THREADS];
    r0[tid] = coord; r1[tid] = objs; r2[tid] = sppos; r3[tid] = sall; rn[tid] = npos;
    __syncthreads();
    #pragma unroll
    for (int o = THREADS / 2; o > 0; o >>= 1) {
        if (tid < o) {
            r0[tid] += r0[tid + o];
            r1[tid] += r1[tid + o];
            r2[tid] += r2[tid + o];
            r3[tid] += r3[tid + o];
            rn[tid] += rn[tid + o];
        }
        __syncthreads();
    }

    if (tid == 0) {
        float np = (float)rn[0];
        float nn = (float)NCELL - np;
        float c  = 5.0f * r0[0] / fmaxf(np, 1.0f);
        float ob = 1.0f * r1[0] / fmaxf(np, 1.0f);
        float no = 0.5f * (r3[0] - r2[0]) / fmaxf(nn, 1.0f);
        out[0] = c + ob + no;
        out[1] = c;
        out[2] = ob;
        out[3] = no;
        out[4] = 0.0f;
        g_counter = 0;   // reset for next graph replay (deterministic)
    }
}

extern "C" void kernel_launch(void* const* d_in, const int* in_sizes, int n_in,
                              void* d_out, int out_size) {
    const float* pred = (const float*)d_in[0];
    const float* bbox = (const float*)d_in[1];
    float* out = (float*)d_out;
    (void)in_sizes; (void)n_in; (void)out_size;

    loss_kernel<<<BLOCKS, THREADS>>>(pred, bbox, out);
}

// round 4
// speedup vs baseline: 1.1859x; 1.0025x over previous
#include <cuda_runtime.h>
#include <math.h>

// Fixed shapes per reference
#define HH    112
#define WW    112
#define AA    9
#define NBOX  768          // B * 24
#define NCELL 3612672      // B*H*W*A
#define NF4   4515840      // total float4s in predictions
#define NTASK 903168       // NF4/5: each task = 5 float4s = 4 records

#define BLOCKS  1184
#define THREADS 256

__device__ float g_partials[BLOCKS];
__device__ int   g_counter = 0;   // zero-inited at module load; last block resets it

// Accurate softplus (used only in the tiny phase-2 tail, ~1500 evals)
__device__ __forceinline__ float softplus_acc(float x) {
    return fmaxf(x, 0.0f) + log1pf(expf(-fabsf(x)));
}

__global__ __launch_bounds__(THREADS) void loss_kernel(const float* __restrict__ pred,
                                                       const float* __restrict__ bbox,
                                                       float* __restrict__ out) {
    // ---------- Phase 1: every block sums softplus over the obj channel ----------
    // Task t covers floats [20t, 20t+19] = 4 records. Obj elements (global idx
    // ≡ 4 mod 5) sit in float4s 5t+1..5t+4 at lanes .x/.y/.z/.w. The float4 at
    // 5t holds only bbox channels and is skipped; every 32B sector is still
    // requested by some lane, so DRAM traffic = one full 72MB pass.
    //
    // softplus sum via log-of-product: sum_i softplus(x_i)
    //   = sum_i max(x_i,0) + log( prod_i (1 + exp(-|x_i|)) )
    // grouped 4 elements per logf. Each term in (1,2], product <= 16: exact
    // range, no overflow; <=3 extra fp32 mult roundings per group (~2e-7 rel).
    const float4* __restrict__ p4 = reinterpret_cast<const float4*>(pred);
    float acc = 0.0f;
    const int stride = gridDim.x * blockDim.x;
    for (int t = blockIdx.x * blockDim.x + threadIdx.x; t < NTASK; t += stride) {
        int b = t * 5;
        float4 c1 = p4[b + 1];
        float4 c2 = p4[b + 2];
        float4 c3 = p4[b + 3];
        float4 c4 = p4[b + 4];
        float x0 = c1.x, x1 = c2.y, x2 = c3.z, x3 = c4.w;

        acc += fmaxf(x0, 0.0f) + fmaxf(x1, 0.0f) + fmaxf(x2, 0.0f) + fmaxf(x3, 0.0f);

        float e0 = expf(-fabsf(x0));
        float e1 = expf(-fabsf(x1));
        float e2 = expf(-fabsf(x2));
        float e3 = expf(-fabsf(x3));
        float p  = (1.0f + e0) * (1.0f + e1);
        float q  = (1.0f + e2) * (1.0f + e3);
        acc += logf(p * q);
    }

    __shared__ float s[THREADS];
    const int tid = threadIdx.x;
    s[tid] = acc;
    __syncthreads();
    #pragma unroll
    for (int o = THREADS / 2; o > 0; o >>= 1) {
        if (tid < o) s[tid] += s[tid + o];
        __syncthreads();
    }

    __shared__ bool is_last;
    if (tid == 0) {
        g_partials[blockIdx.x] = s[0];
        __threadfence();
        int old = atomicAdd(&g_counter, 1);
        is_last = (old == (int)gridDim.x - 1);
    }
    __syncthreads();
    if (!is_last) return;

    // ---------- Phase 2: last block only — targets, dedup, gather, finalize ----------
    __shared__ int   s_key[NBOX];
    __shared__ float s_t[NBOX][4];

    // anchors computed in double on device (bit-identical to R1/R3 passes)
    float aw[AA], ah[AA];
    {
        const double S[3] = {32.0, 64.0, 128.0};
        const double R[3] = {0.5, 1.0, 2.0};
        #pragma unroll
        for (int i = 0; i < AA; i++) {
            double sd = S[i / 3], rd = R[i % 3];
            aw[i] = (float)(sd * sqrt(rd) / 224.0);
            ah[i] = (float)(sd / sqrt(rd) / 224.0);
        }
    }

    for (int idx = tid; idx < NBOX; idx += THREADS) {
        float cx = bbox[idx * 4 + 0];
        float cy = bbox[idx * 4 + 1];
        float w  = bbox[idx * 4 + 2];
        float h  = bbox[idx * 4 + 3];
        bool valid = (cx != 0.0f) || (cy != 0.0f) || (w != 0.0f) || (h != 0.0f);
        if (!valid) { s_key[idx] = -1; continue; }

        int gx = (int)floorf(cx * (float)WW); gx = min(max(gx, 0), WW - 1);
        int gy = (int)floorf(cy * (float)HH); gy = min(max(gy, 0), HH - 1);

        float wh = w * h;
        int best = 0; float bi = -1e30f;
        #pragma unroll
        for (int a = 0; a < AA; a++) {
            float inter = fminf(w, aw[a]) * fminf(h, ah[a]);
            float uni   = wh + aw[a] * ah[a] - inter;
            float iou   = inter / (uni + 1e-16f);
            if (iou > bi) { bi = iou; best = a; }   // first max wins (strict >)
        }

        int b = idx / 24;
        s_key[idx]  = ((b * HH + gy) * WW + gx) * AA + best;
        s_t[idx][0] = cx * (float)WW - (float)gx;
        s_t[idx][1] = cy * (float)HH - (float)gy;
        s_t[idx][2] = logf(w / aw[best] + 1e-16f);
        s_t[idx][3] = logf(h / ah[best] + 1e-16f);
    }
    __syncthreads();

    float coord = 0.0f, objs = 0.0f, sppos = 0.0f;
    int npos = 0;

    for (int idx = tid; idx < NBOX; idx += THREADS) {
        int key = s_key[idx];
        if (key < 0) continue;
        // collisions only possible within the same batch; last scatter wins
        int bend = ((idx / 24) + 1) * 24;
        bool win = true;
        for (int j = idx + 1; j < bend; j++) {
            if (s_key[j] == key) { win = false; break; }
        }
        if (!win) continue;

        const float* p = pred + (long long)key * 5;
        float d0 = p[0] - s_t[idx][0];
        float d1 = p[1] - s_t[idx][1];
        float d2 = p[2] - s_t[idx][2];
        float d3 = p[3] - s_t[idx][3];
        coord += d0 * d0 + d1 * d1 + d2 * d2 + d3 * d3;
        float o = p[4];
        objs  += softplus_acc(-o);
        sppos += softplus_acc(o);
        npos++;
    }

    // reduce partials written by all blocks (fence+atomic chain makes them visible)
    float sall = 0.0f;
    for (int i = tid; i < BLOCKS; i += THREADS) sall += g_partials[i];

    __shared__ float r0[THREADS], r1[THREADS], r2[THREADS], r3[THREADS];
    __shared__ int   rn[THREADS];
    r0[tid] = coord; r1[tid] = objs; r2[tid] = sppos; r3[tid] = sall; rn[tid] = npos;
    __syncthreads();
    #pragma unroll
    for (int o = THREADS / 2; o > 0; o >>= 1) {
        if (tid < o) {
            r0[tid] += r0[tid + o];
            r1[tid] += r1[tid + o];
            r2[tid] += r2[tid + o];
            r3[tid] += r3[tid + o];
            rn[tid] += rn[tid + o];
        }
        __syncthreads();
    }

    if (tid == 0) {
        float np = (float)rn[0];
        float nn = (float)NCELL - np;
        float c  = 5.0f * r0[0] / fmaxf(np, 1.0f);
        float ob = 1.0f * r1[0] / fmaxf(np, 1.0f);
        float no = 0.5f * (r3[0] - r2[0]) / fmaxf(nn, 1.0f);
        out[0] = c + ob + no;
        out[1] = c;
        out[2] = ob;
        out[3] = no;
        out[4] = 0.0f;
        g_counter = 0;   // reset for next graph replay (deterministic)
    }
}

extern "C" void kernel_launch(void* const* d_in, const int* in_sizes, int n_in,
                              void* d_out, int out_size) {
    const float* pred = (const float*)d_in[0];
    const float* bbox = (const float*)d_in[1];
    float* out = (float*)d_out;
    (void)in_sizes; (void)n_in; (void)out_size;

    loss_kernel<<<BLOCKS, THREADS>>>(pred, bbox, out);
}